// round 16
// baseline (speedup 1.0000x reference)
#include <cuda_runtime.h>
#include <cuda_bf16.h>
#include <cstdint>

#define BB 256
#define TT 2048
#define II 128
#define HH 256
#define AA 8

typedef unsigned long long ull;

// scratch: xproj fp32 + pre-split bf16 copies of x and W_ih
__device__ float g_xproj[(size_t)BB * TT * HH];                  // 512MB
__device__ __nv_bfloat16 g_xh[(size_t)BB * TT * II];             // 128MB
__device__ __nv_bfloat16 g_xl[(size_t)BB * TT * II];             // 128MB
__device__ __nv_bfloat16 g_wh[HH * II];
__device__ __nv_bfloat16 g_wl[HH * II];

__device__ __forceinline__ ull ffma2(ull a, ull b, ull c) {
  ull d;
  asm("fma.rn.f32x2 %0, %1, %2, %3;" : "=l"(d) : "l"(a), "l"(b), "l"(c));
  return d;
}
__device__ __forceinline__ ull add2(ull a, ull b) {
  ull d;
  asm("add.rn.f32x2 %0, %1, %2;" : "=l"(d) : "l"(a), "l"(b));
  return d;
}
__device__ __forceinline__ ull pack2(float lo, float hi) {
  ull d;
  asm("mov.b64 %0, {%1, %2};" : "=l"(d) : "f"(lo), "f"(hi));
  return d;
}
__device__ __forceinline__ float hsum2(ull v) {
  float lo, hi;
  asm("mov.b64 {%0, %1}, %2;" : "=f"(lo), "=f"(hi) : "l"(v));
  return lo + hi;
}
__device__ __forceinline__ uint32_t smem_u32(const void* p) {
  uint32_t a;
  asm("{ .reg .u64 t; cvta.to.shared.u64 t, %1; cvt.u32.u64 %0, t; }"
      : "=r"(a) : "l"(p));
  return a;
}
__device__ __forceinline__ void ldsm_x4(uint32_t addr, uint32_t& r0,
                                        uint32_t& r1, uint32_t& r2,
                                        uint32_t& r3) {
  asm volatile(
      "ldmatrix.sync.aligned.m8n8.x4.shared.b16 {%0,%1,%2,%3}, [%4];"
      : "=r"(r0), "=r"(r1), "=r"(r2), "=r"(r3) : "r"(addr));
}
__device__ __forceinline__ void mma16816(float* d, const uint32_t* a,
                                         uint32_t b0, uint32_t b1) {
  asm volatile(
      "mma.sync.aligned.m16n8k16.row.col.f32.bf16.bf16.f32 "
      "{%0,%1,%2,%3}, {%4,%5,%6,%7}, {%8,%9}, {%0,%1,%2,%3};"
      : "+f"(d[0]), "+f"(d[1]), "+f"(d[2]), "+f"(d[3])
      : "r"(a[0]), "r"(a[1]), "r"(a[2]), "r"(a[3]), "r"(b0), "r"(b1));
}

#define XSTR 136  // bf16 row stride: 272B -> ldmatrix rows hit all 32 banks

// ---------------------------------------------------------------------------
// Kernel 0: global hi/lo bf16 split of x and W_ih (DRAM-bound, ~50us).
// Same split arithmetic as the proven R15 in-kernel conversion.
// ---------------------------------------------------------------------------
__global__ void __launch_bounds__(512) convert_kernel(
    const float* __restrict__ x, const float* __restrict__ W_ih) {
  const size_t gid = (size_t)blockIdx.x * 512 + threadIdx.x;
  const float2* x2 = reinterpret_cast<const float2*>(x);
  uint32_t* xh2 = reinterpret_cast<uint32_t*>(g_xh);
  uint32_t* xl2 = reinterpret_cast<uint32_t*>(g_xl);
  #pragma unroll
  for (int i = 0; i < 8; ++i) {
    size_t idx = gid + (size_t)i * 4194304;  // 8192 blocks * 512 threads
    float2 v = __ldg(x2 + idx);
    __nv_bfloat162 h = __floats2bfloat162_rn(v.x, v.y);
    float r0 = v.x - __bfloat162float(h.x);
    float r1 = v.y - __bfloat162float(h.y);
    __nv_bfloat162 l = __floats2bfloat162_rn(r0, r1);
    xh2[idx] = *reinterpret_cast<uint32_t*>(&h);
    xl2[idx] = *reinterpret_cast<uint32_t*>(&l);
  }
  if (gid < HH * II / 2) {
    const float2* w2 = reinterpret_cast<const float2*>(W_ih);
    float2 v = __ldg(w2 + gid);
    __nv_bfloat162 h = __floats2bfloat162_rn(v.x, v.y);
    float r0 = v.x - __bfloat162float(h.x);
    float r1 = v.y - __bfloat162float(h.y);
    __nv_bfloat162 l = __floats2bfloat162_rn(r0, r1);
    reinterpret_cast<uint32_t*>(g_wh)[gid] = *reinterpret_cast<uint32_t*>(&h);
    reinterpret_cast<uint32_t*>(g_wl)[gid] = *reinterpret_cast<uint32_t*>(&l);
  }
}

// ---------------------------------------------------------------------------
// Kernel 1: xproj via mma.sync bf16, 3-term hi/lo split — MMA/ldsm/epilogue
// bit-identical to the proven R15 kernel; staging is now a pure
// LDG.128 -> STS.128 copy of the pre-split bf16 arrays.
// ---------------------------------------------------------------------------
__global__ void __launch_bounds__(512) xproj_kernel(
    const float* __restrict__ x_unused, const float* __restrict__ W_unused) {
  extern __shared__ __align__(16) char smem[];
  __nv_bfloat16* sb = reinterpret_cast<__nv_bfloat16*>(smem);
  __nv_bfloat16* xh = sb;                   // [128][XSTR]
  __nv_bfloat16* xl = sb + 128 * XSTR;
  __nv_bfloat16* wh = sb + 2 * 128 * XSTR;  // [256][XSTR]
  __nv_bfloat16* wl = sb + 2 * 128 * XSTR + 256 * XSTR;

  const int tid = threadIdx.x;
  const int wid = tid >> 5, lane = tid & 31;
  const size_t rowbase = (size_t)blockIdx.x * 128;

  // ---- stage A (x tile): pure 16B copies, 2048 chunks per piece ----
  {
    const uint4* srch =
        reinterpret_cast<const uint4*>(g_xh + rowbase * II);
    const uint4* srcl =
        reinterpret_cast<const uint4*>(g_xl + rowbase * II);
    #pragma unroll
    for (int it = 0; it < 4; ++it) {
      int idx = it * 512 + tid;           // chunk: row = idx>>4, kc = idx&15
      int row = idx >> 4, kc = idx & 15;
      uint4 vh = __ldg(srch + idx);
      uint4 vl = __ldg(srcl + idx);
      *reinterpret_cast<uint4*>(
          reinterpret_cast<char*>(xh) + row * (XSTR * 2) + kc * 16) = vh;
      *reinterpret_cast<uint4*>(
          reinterpret_cast<char*>(xl) + row * (XSTR * 2) + kc * 16) = vl;
    }
  }
  // ---- stage B (W): 4096 chunks per piece ----
  {
    const uint4* srch = reinterpret_cast<const uint4*>(g_wh);
    const uint4* srcl = reinterpret_cast<const uint4*>(g_wl);
    #pragma unroll
    for (int it = 0; it < 8; ++it) {
      int idx = it * 512 + tid;
      int row = idx >> 4, kc = idx & 15;
      uint4 vh = __ldg(srch + idx);
      uint4 vl = __ldg(srcl + idx);
      *reinterpret_cast<uint4*>(
          reinterpret_cast<char*>(wh) + row * (XSTR * 2) + kc * 16) = vh;
      *reinterpret_cast<uint4*>(
          reinterpret_cast<char*>(wl) + row * (XSTR * 2) + kc * 16) = vl;
    }
  }
  __syncthreads();

  // ---- MMA phase (identical to R15) ----
  const int mbase = (wid & 3) * 32;
  const int nbase = (wid >> 2) * 64;

  const int arow = lane & 15, ahalf = lane >> 4;
  const int brow = lane & 7, bk = (lane >> 3) & 1, btile = lane >> 4;

  const uint32_t xh_u = smem_u32(xh), xl_u = smem_u32(xl);
  const uint32_t wh_u = smem_u32(wh), wl_u = smem_u32(wl);
  const uint32_t aoff = (uint32_t)(((mbase + arow) * XSTR + 8 * ahalf) * 2);
  const uint32_t boff =
      (uint32_t)(((nbase + btile * 8 + brow) * XSTR + 8 * bk) * 2);

  float acc[2][8][4];
  #pragma unroll
  for (int mt = 0; mt < 2; ++mt)
    #pragma unroll
    for (int nt = 0; nt < 8; ++nt)
      #pragma unroll
      for (int u = 0; u < 4; ++u) acc[mt][nt][u] = 0.0f;

  #pragma unroll
  for (int term = 0; term < 3; ++term) {
    const uint32_t abase = (term == 1 ? xl_u : xh_u) + aoff;
    const uint32_t bbase = (term == 2 ? wl_u : wh_u) + boff;
    for (int k8 = 0; k8 < 8; ++k8) {
      const uint32_t koff = (uint32_t)(k8 * 32);
      uint32_t a[2][4];
      #pragma unroll
      for (int mt = 0; mt < 2; ++mt) {
        ldsm_x4(abase + koff + (uint32_t)(mt * 16 * XSTR * 2),
                a[mt][0], a[mt][1], a[mt][2], a[mt][3]);
      }
      #pragma unroll
      for (int ntp = 0; ntp < 4; ++ntp) {
        uint32_t b0, b1, b2, b3;
        ldsm_x4(bbase + koff + (uint32_t)(ntp * 16 * XSTR * 2), b0, b1, b2,
                b3);
        #pragma unroll
        for (int mt = 0; mt < 2; ++mt) {
          mma16816(acc[mt][2 * ntp],     a[mt], b0, b1);
          mma16816(acc[mt][2 * ntp + 1], a[mt], b2, b3);
        }
      }
    }
  }

  // ---- epilogue (identical to R15) ----
  #pragma unroll
  for (int mt = 0; mt < 2; ++mt) {
    #pragma unroll
    for (int nt = 0; nt < 8; ++nt) {
      int r0 = mbase + mt * 16 + (lane >> 2);
      int c = nbase + nt * 8 + 2 * (lane & 3);
      float* p = g_xproj + (rowbase + r0) * HH + c;
      *reinterpret_cast<float2*>(p) =
          make_float2(acc[mt][nt][0], acc[mt][nt][1]);
      *reinterpret_cast<float2*>(p + 8 * HH) =
          make_float2(acc[mt][nt][2], acc[mt][nt][3]);
    }
  }
}

// ---------------------------------------------------------------------------
// Kernel 2: recurrence — VERBATIM the measured-2.455ms version.
// ---------------------------------------------------------------------------
__global__ void __launch_bounds__(512, 1) recurrence_kernel(
    const float* __restrict__ hx, const float* __restrict__ W_hh,
    const float* __restrict__ W_actor, const float* __restrict__ W_critic,
    float* __restrict__ out) {
  extern __shared__ float smemf[];
  ulonglong2* sW = reinterpret_cast<ulonglong2*>(smemf);  // 12*512 u2
  float* shb = smemf + 12 * 512 * 4;                      // [2 parity][2 b][288]

  const int tid = threadIdx.x;
  const int JQ = tid >> 3;
  const int KH = tid & 7;
  const int jb = JQ * 4;
  const int kb = KH * 32;
  const int b0g = blockIdx.x * 2;

  const int jf = JQ * 4 + (KH & 3);
  const int bf = KH >> 2;

  ull wr[4][10];
  #pragma unroll
  for (int j = 0; j < 4; ++j) {
    const float4* wp =
        reinterpret_cast<const float4*>(W_hh + (jb + j) * HH + kb);
    #pragma unroll
    for (int q = 0; q < 5; ++q) {
      float4 f = __ldg(wp + q);
      wr[j][2 * q]     = pack2(f.x, f.y);
      wr[j][2 * q + 1] = pack2(f.z, f.w);
    }
  }
  #pragma unroll
  for (int q = 5; q < 8; ++q) {
    #pragma unroll
    for (int j = 0; j < 4; ++j) {
      float4 f = __ldg(reinterpret_cast<const float4*>(
          W_hh + (jb + j) * HH + kb) + q);
      ulonglong2 v;
      v.x = pack2(f.x, f.y);
      v.y = pack2(f.z, f.w);
      sW[((q - 5) * 4 + j) * 512 + tid] = v;
    }
  }

  float h_old = hx[(b0g + bf) * HH + jf];
  shb[bf * 288 + (jf >> 5) * 36 + (jf & 31)] = h_old;
  __syncthreads();

  const float* xqp = g_xproj + ((size_t)(b0g + bf) * TT) * HH + jf;
  float xq_cur = __ldg(xqp);

  for (int t = 0; t < TT; ++t) {
    const int rp = t & 1;
    float xq_nxt = 0.0f;
    if (t + 1 < TT) xq_nxt = __ldg(xqp + (size_t)(t + 1) * HH);

    const float* hbase = shb + rp * 576;
    const ulonglong2* hp0 =
        reinterpret_cast<const ulonglong2*>(hbase + KH * 36);
    const ulonglong2* hp1 =
        reinterpret_cast<const ulonglong2*>(hbase + 288 + KH * 36);

    ull a[8];
    #pragma unroll
    for (int i = 0; i < 8; ++i) a[i] = 0ull;

    #pragma unroll
    for (int q = 0; q < 8; ++q) {
      ulonglong2 v0 = hp0[q];
      ulonglong2 v1 = hp1[q];
      if (q < 5) {
        #pragma unroll
        for (int j = 0; j < 4; ++j) {
          a[j]     = ffma2(wr[j][2 * q],     v0.x, a[j]);
          a[j]     = ffma2(wr[j][2 * q + 1], v0.y, a[j]);
          a[4 + j] = ffma2(wr[j][2 * q],     v1.x, a[4 + j]);
          a[4 + j] = ffma2(wr[j][2 * q + 1], v1.y, a[4 + j]);
        }
      } else {
        #pragma unroll
        for (int j = 0; j < 4; ++j) {
          ulonglong2 wv = sW[((q - 5) * 4 + j) * 512 + tid];
          a[j]     = ffma2(wv.x, v0.x, a[j]);
          a[j]     = ffma2(wv.y, v0.y, a[j]);
          a[4 + j] = ffma2(wv.x, v1.x, a[4 + j]);
          a[4 + j] = ffma2(wv.y, v1.y, a[4 + j]);
        }
      }
    }

    const bool s0 = (tid & 1), s1 = (tid & 2), s2 = (tid & 4);
    ull w4[4];
    #pragma unroll
    for (int r = 0; r < 4; ++r) {
      ull keep = s0 ? a[2 * r + 1] : a[2 * r];
      ull give = s0 ? a[2 * r]     : a[2 * r + 1];
      ull recv = __shfl_xor_sync(0xffffffffu, give, 1);
      w4[r] = add2(keep, recv);
    }
    ull w2[2];
    #pragma unroll
    for (int r = 0; r < 2; ++r) {
      ull keep = s1 ? w4[2 * r + 1] : w4[2 * r];
      ull give = s1 ? w4[2 * r]     : w4[2 * r + 1];
      ull recv = __shfl_xor_sync(0xffffffffu, give, 2);
      w2[r] = add2(keep, recv);
    }
    ull keep = s2 ? w2[1] : w2[0];
    ull give = s2 ? w2[0] : w2[1];
    ull recv = __shfl_xor_sync(0xffffffffu, give, 4);
    ull tot = add2(keep, recv);

    float p = hsum2(tot) + xq_cur;
    h_old = 0.8f * h_old + 0.2f * fmaxf(p, 0.0f);
    shb[(rp ^ 1) * 576 + bf * 288 + (jf >> 5) * 36 + (jf & 31)] = h_old;
    xq_cur = xq_nxt;
    __syncthreads();
  }

  const float* hf0 = shb;
  const float* hf1 = shb + 288;
  float* out_actor  = out;
  float* out_critic = out + BB * AA;
  float* out_hx     = out + BB * AA + BB;

  if (tid < HH) {
    int pj = (tid >> 5) * 36 + (tid & 31);
    out_hx[b0g * HH + tid]       = hf0[pj];
    out_hx[(b0g + 1) * HH + tid] = hf1[pj];
  }

  const int wid = tid >> 5, lane = tid & 31;
  if (wid < AA) {
    float pa0 = 0.f, pa1 = 0.f;
    for (int jj = lane; jj < HH; jj += 32) {
      int pj = (jj >> 5) * 36 + (jj & 31);
      float wa = W_actor[wid * HH + jj];
      pa0 += wa * hf0[pj];
      pa1 += wa * hf1[pj];
    }
    #pragma unroll
    for (int off = 16; off; off >>= 1) {
      pa0 += __shfl_down_sync(0xffffffffu, pa0, off);
      pa1 += __shfl_down_sync(0xffffffffu, pa1, off);
    }
    if (lane == 0) {
      out_actor[b0g * AA + wid]       = pa0;
      out_actor[(b0g + 1) * AA + wid] = pa1;
    }
  }
  if (wid == 8) {
    float pc0 = 0.f, pc1 = 0.f;
    for (int jj = lane; jj < HH; jj += 32) {
      int pj = (jj >> 5) * 36 + (jj & 31);
      float wc = W_critic[jj];
      pc0 += wc * hf0[pj];
      pc1 += wc * hf1[pj];
    }
    #pragma unroll
    for (int off = 16; off; off >>= 1) {
      pc0 += __shfl_down_sync(0xffffffffu, pc0, off);
      pc1 += __shfl_down_sync(0xffffffffu, pc1, off);
    }
    if (lane == 0) {
      out_critic[b0g]     = pc0;
      out_critic[b0g + 1] = pc1;
    }
  }
}

// ---------------------------------------------------------------------------
extern "C" void kernel_launch(void* const* d_in, const int* in_sizes, int n_in,
                              void* d_out, int out_size) {
  const float* x        = (const float*)d_in[0];
  const float* hx       = (const float*)d_in[1];
  const float* W_ih     = (const float*)d_in[2];
  const float* W_hh     = (const float*)d_in[3];
  const float* W_actor  = (const float*)d_in[4];
  const float* W_critic = (const float*)d_in[5];
  float* out = (float*)d_out;

  const int smem1 = (2 * 128 * XSTR + 2 * 256 * XSTR) * 2;  // 208896 B
  const int smem2 = 98304 + 4608;

  cudaFuncSetAttribute(xproj_kernel,
                       cudaFuncAttributeMaxDynamicSharedMemorySize, smem1);
  cudaFuncSetAttribute(recurrence_kernel,
                       cudaFuncAttributeMaxDynamicSharedMemorySize, smem2);

  convert_kernel<<<8192, 512>>>(x, W_ih);
  xproj_kernel<<<(BB * TT) / 128, 512, smem1>>>(x, W_ih);
  recurrence_kernel<<<BB / 2, 512, smem2>>>(hx, W_hh, W_actor, W_critic, out);
}

// round 17
// speedup vs baseline: 1.0281x; 1.0281x over previous
#include <cuda_runtime.h>
#include <cuda_bf16.h>
#include <cstdint>

#define BB 256
#define TT 2048
#define II 128
#define HH 256
#define AA 8

typedef unsigned long long ull;

// scratch: xproj fp32 + pre-split bf16 W_ih
__device__ float g_xproj[(size_t)BB * TT * HH];     // 512MB
__device__ __nv_bfloat16 g_wh[HH * II];
__device__ __nv_bfloat16 g_wl[HH * II];

__device__ __forceinline__ ull ffma2(ull a, ull b, ull c) {
  ull d;
  asm("fma.rn.f32x2 %0, %1, %2, %3;" : "=l"(d) : "l"(a), "l"(b), "l"(c));
  return d;
}
__device__ __forceinline__ ull add2(ull a, ull b) {
  ull d;
  asm("add.rn.f32x2 %0, %1, %2;" : "=l"(d) : "l"(a), "l"(b));
  return d;
}
__device__ __forceinline__ ull pack2(float lo, float hi) {
  ull d;
  asm("mov.b64 %0, {%1, %2};" : "=l"(d) : "f"(lo), "f"(hi));
  return d;
}
__device__ __forceinline__ float hsum2(ull v) {
  float lo, hi;
  asm("mov.b64 {%0, %1}, %2;" : "=f"(lo), "=f"(hi) : "l"(v));
  return lo + hi;
}
__device__ __forceinline__ uint32_t smem_u32(const void* p) {
  uint32_t a;
  asm("{ .reg .u64 t; cvta.to.shared.u64 t, %1; cvt.u32.u64 %0, t; }"
      : "=r"(a) : "l"(p));
  return a;
}
__device__ __forceinline__ uint32_t bf16pair(float a, float b) {
  __nv_bfloat162 t = __floats2bfloat162_rn(a, b);  // a -> low half
  return *reinterpret_cast<uint32_t*>(&t);
}
__device__ __forceinline__ void ldsm_x4(uint32_t addr, uint32_t& r0,
                                        uint32_t& r1, uint32_t& r2,
                                        uint32_t& r3) {
  asm volatile(
      "ldmatrix.sync.aligned.m8n8.x4.shared.b16 {%0,%1,%2,%3}, [%4];"
      : "=r"(r0), "=r"(r1), "=r"(r2), "=r"(r3) : "r"(addr));
}
__device__ __forceinline__ void mma16816(float* d, const uint32_t* a,
                                         uint32_t b0, uint32_t b1) {
  asm volatile(
      "mma.sync.aligned.m16n8k16.row.col.f32.bf16.bf16.f32 "
      "{%0,%1,%2,%3}, {%4,%5,%6,%7}, {%8,%9}, {%0,%1,%2,%3};"
      : "+f"(d[0]), "+f"(d[1]), "+f"(d[2]), "+f"(d[3])
      : "r"(a[0]), "r"(a[1]), "r"(a[2]), "r"(a[3]), "r"(b0), "r"(b1));
}

#define XSTR 136  // bf16 row stride: 272B -> ldmatrix rows hit all 32 banks

// ---------------------------------------------------------------------------
// Kernel 0: hi/lo bf16 split of W_ih only (32K elements, ~3us).
// ---------------------------------------------------------------------------
__global__ void __launch_bounds__(512) splitw_kernel(
    const float* __restrict__ W_ih) {
  const int gid = blockIdx.x * 512 + threadIdx.x;
  if (gid < HH * II / 2) {
    const float2* w2 = reinterpret_cast<const float2*>(W_ih);
    float2 v = __ldg(w2 + gid);
    __nv_bfloat162 h = __floats2bfloat162_rn(v.x, v.y);
    float r0 = v.x - __bfloat162float(h.x);
    float r1 = v.y - __bfloat162float(h.y);
    __nv_bfloat162 l = __floats2bfloat162_rn(r0, r1);
    reinterpret_cast<uint32_t*>(g_wh)[gid] = *reinterpret_cast<uint32_t*>(&h);
    reinterpret_cast<uint32_t*>(g_wl)[gid] = *reinterpret_cast<uint32_t*>(&l);
  }
}

// ---------------------------------------------------------------------------
// Kernel 1: xproj via mma.sync bf16, 3-term hi/lo split (xh*Wh + xl*Wh +
// xh*Wl). Same tiling/layout as the proven 2820us kernel; deltas:
//  - W staged as pure 16B copies of pre-split g_wh/g_wl
//  - fused term loop shares A and B fragments: 96 ldsm / 384 mma per warp
// ---------------------------------------------------------------------------
__global__ void __launch_bounds__(512) xproj_kernel(
    const float* __restrict__ x) {
  extern __shared__ __align__(16) char smem[];
  __nv_bfloat16* sb = reinterpret_cast<__nv_bfloat16*>(smem);
  __nv_bfloat16* xh = sb;                   // [128][XSTR]
  __nv_bfloat16* xl = sb + 128 * XSTR;
  __nv_bfloat16* wh = sb + 2 * 128 * XSTR;  // [256][XSTR]
  __nv_bfloat16* wl = sb + 2 * 128 * XSTR + 256 * XSTR;

  const int tid = threadIdx.x;
  const int wid = tid >> 5, lane = tid & 31;
  const size_t rowbase = (size_t)blockIdx.x * 128;

  // ---- stage x tile: fp32 -> hi/lo bf16 (inline, proven) ----
  const float2* xg2 = reinterpret_cast<const float2*>(x + rowbase * II);
  #pragma unroll
  for (int it = 0; it < 16; ++it) {
    int idx = it * 512 + tid;
    float2 v = __ldg(xg2 + idx);
    int row = idx >> 6, k2 = idx & 63;
    __nv_bfloat16 h0 = __float2bfloat16(v.x);
    __nv_bfloat16 h1 = __float2bfloat16(v.y);
    float r0 = v.x - __bfloat162float(h0);
    float r1 = v.y - __bfloat162float(h1);
    int e = row * XSTR + 2 * k2;
    *reinterpret_cast<uint32_t*>(xh + e) = bf16pair(v.x, v.y);
    *reinterpret_cast<uint32_t*>(xl + e) = bf16pair(r0, r1);
  }
  // ---- stage W: pure 16B copies of pre-split arrays ----
  {
    const uint4* srch = reinterpret_cast<const uint4*>(g_wh);
    const uint4* srcl = reinterpret_cast<const uint4*>(g_wl);
    #pragma unroll
    for (int it = 0; it < 8; ++it) {
      int idx = it * 512 + tid;
      int row = idx >> 4, kc = idx & 15;
      uint4 vh = __ldg(srch + idx);
      uint4 vl = __ldg(srcl + idx);
      *reinterpret_cast<uint4*>(
          reinterpret_cast<char*>(wh) + row * (XSTR * 2) + kc * 16) = vh;
      *reinterpret_cast<uint4*>(
          reinterpret_cast<char*>(wl) + row * (XSTR * 2) + kc * 16) = vl;
    }
  }
  __syncthreads();

  // ---- MMA phase (fused 3-term, shared fragments) ----
  const int mbase = (wid & 3) * 32;
  const int nbase = (wid >> 2) * 64;

  const int arow = lane & 15, ahalf = lane >> 4;
  const int brow = lane & 7, bk = (lane >> 3) & 1, btile = lane >> 4;

  const uint32_t xh_u = smem_u32(xh), xl_u = smem_u32(xl);
  const uint32_t wh_u = smem_u32(wh), wl_u = smem_u32(wl);
  const uint32_t aoff = (uint32_t)(((mbase + arow) * XSTR + 8 * ahalf) * 2);
  const uint32_t boff =
      (uint32_t)(((nbase + btile * 8 + brow) * XSTR + 8 * bk) * 2);

  float acc[2][8][4];
  #pragma unroll
  for (int mt = 0; mt < 2; ++mt)
    #pragma unroll
    for (int nt = 0; nt < 8; ++nt)
      #pragma unroll
      for (int u = 0; u < 4; ++u) acc[mt][nt][u] = 0.0f;

  for (int k8 = 0; k8 < 8; ++k8) {
    const uint32_t koff = (uint32_t)(k8 * 32);
    uint32_t ah[2][4], al[2][4];
    #pragma unroll
    for (int mt = 0; mt < 2; ++mt) {
      const uint32_t astep = koff + (uint32_t)(mt * 16 * XSTR * 2);
      ldsm_x4(xh_u + aoff + astep, ah[mt][0], ah[mt][1], ah[mt][2],
              ah[mt][3]);
      ldsm_x4(xl_u + aoff + astep, al[mt][0], al[mt][1], al[mt][2],
              al[mt][3]);
    }
    #pragma unroll
    for (int ntp = 0; ntp < 4; ++ntp) {
      const uint32_t bstep = koff + (uint32_t)(ntp * 16 * XSTR * 2);
      uint32_t bh0, bh1, bh2, bh3, bl0, bl1, bl2, bl3;
      ldsm_x4(wh_u + boff + bstep, bh0, bh1, bh2, bh3);
      ldsm_x4(wl_u + boff + bstep, bl0, bl1, bl2, bl3);
      #pragma unroll
      for (int mt = 0; mt < 2; ++mt) {
        mma16816(acc[mt][2 * ntp],     ah[mt], bh0, bh1);
        mma16816(acc[mt][2 * ntp + 1], ah[mt], bh2, bh3);
        mma16816(acc[mt][2 * ntp],     al[mt], bh0, bh1);
        mma16816(acc[mt][2 * ntp + 1], al[mt], bh2, bh3);
        mma16816(acc[mt][2 * ntp],     ah[mt], bl0, bl1);
        mma16816(acc[mt][2 * ntp + 1], ah[mt], bl2, bl3);
      }
    }
  }

  // ---- epilogue (identical to R15) ----
  #pragma unroll
  for (int mt = 0; mt < 2; ++mt) {
    #pragma unroll
    for (int nt = 0; nt < 8; ++nt) {
      int r0 = mbase + mt * 16 + (lane >> 2);
      int c = nbase + nt * 8 + 2 * (lane & 3);
      float* p = g_xproj + (rowbase + r0) * HH + c;
      *reinterpret_cast<float2*>(p) =
          make_float2(acc[mt][nt][0], acc[mt][nt][1]);
      *reinterpret_cast<float2*>(p + 8 * HH) =
          make_float2(acc[mt][nt][2], acc[mt][nt][3]);
    }
  }
}

// ---------------------------------------------------------------------------
// Kernel 2: recurrence — VERBATIM the measured-2.455ms version.
// ---------------------------------------------------------------------------
__global__ void __launch_bounds__(512, 1) recurrence_kernel(
    const float* __restrict__ hx, const float* __restrict__ W_hh,
    const float* __restrict__ W_actor, const float* __restrict__ W_critic,
    float* __restrict__ out) {
  extern __shared__ float smemf[];
  ulonglong2* sW = reinterpret_cast<ulonglong2*>(smemf);  // 12*512 u2
  float* shb = smemf + 12 * 512 * 4;                      // [2 parity][2 b][288]

  const int tid = threadIdx.x;
  const int JQ = tid >> 3;
  const int KH = tid & 7;
  const int jb = JQ * 4;
  const int kb = KH * 32;
  const int b0g = blockIdx.x * 2;

  const int jf = JQ * 4 + (KH & 3);
  const int bf = KH >> 2;

  ull wr[4][10];
  #pragma unroll
  for (int j = 0; j < 4; ++j) {
    const float4* wp =
        reinterpret_cast<const float4*>(W_hh + (jb + j) * HH + kb);
    #pragma unroll
    for (int q = 0; q < 5; ++q) {
      float4 f = __ldg(wp + q);
      wr[j][2 * q]     = pack2(f.x, f.y);
      wr[j][2 * q + 1] = pack2(f.z, f.w);
    }
  }
  #pragma unroll
  for (int q = 5; q < 8; ++q) {
    #pragma unroll
    for (int j = 0; j < 4; ++j) {
      float4 f = __ldg(reinterpret_cast<const float4*>(
          W_hh + (jb + j) * HH + kb) + q);
      ulonglong2 v;
      v.x = pack2(f.x, f.y);
      v.y = pack2(f.z, f.w);
      sW[((q - 5) * 4 + j) * 512 + tid] = v;
    }
  }

  float h_old = hx[(b0g + bf) * HH + jf];
  shb[bf * 288 + (jf >> 5) * 36 + (jf & 31)] = h_old;
  __syncthreads();

  const float* xqp = g_xproj + ((size_t)(b0g + bf) * TT) * HH + jf;
  float xq_cur = __ldg(xqp);

  for (int t = 0; t < TT; ++t) {
    const int rp = t & 1;
    float xq_nxt = 0.0f;
    if (t + 1 < TT) xq_nxt = __ldg(xqp + (size_t)(t + 1) * HH);

    const float* hbase = shb + rp * 576;
    const ulonglong2* hp0 =
        reinterpret_cast<const ulonglong2*>(hbase + KH * 36);
    const ulonglong2* hp1 =
        reinterpret_cast<const ulonglong2*>(hbase + 288 + KH * 36);

    ull a[8];
    #pragma unroll
    for (int i = 0; i < 8; ++i) a[i] = 0ull;

    #pragma unroll
    for (int q = 0; q < 8; ++q) {
      ulonglong2 v0 = hp0[q];
      ulonglong2 v1 = hp1[q];
      if (q < 5) {
        #pragma unroll
        for (int j = 0; j < 4; ++j) {
          a[j]     = ffma2(wr[j][2 * q],     v0.x, a[j]);
          a[j]     = ffma2(wr[j][2 * q + 1], v0.y, a[j]);
          a[4 + j] = ffma2(wr[j][2 * q],     v1.x, a[4 + j]);
          a[4 + j] = ffma2(wr[j][2 * q + 1], v1.y, a[4 + j]);
        }
      } else {
        #pragma unroll
        for (int j = 0; j < 4; ++j) {
          ulonglong2 wv = sW[((q - 5) * 4 + j) * 512 + tid];
          a[j]     = ffma2(wv.x, v0.x, a[j]);
          a[j]     = ffma2(wv.y, v0.y, a[j]);
          a[4 + j] = ffma2(wv.x, v1.x, a[4 + j]);
          a[4 + j] = ffma2(wv.y, v1.y, a[4 + j]);
        }
      }
    }

    const bool s0 = (tid & 1), s1 = (tid & 2), s2 = (tid & 4);
    ull w4[4];
    #pragma unroll
    for (int r = 0; r < 4; ++r) {
      ull keep = s0 ? a[2 * r + 1] : a[2 * r];
      ull give = s0 ? a[2 * r]     : a[2 * r + 1];
      ull recv = __shfl_xor_sync(0xffffffffu, give, 1);
      w4[r] = add2(keep, recv);
    }
    ull w2[2];
    #pragma unroll
    for (int r = 0; r < 2; ++r) {
      ull keep = s1 ? w4[2 * r + 1] : w4[2 * r];
      ull give = s1 ? w4[2 * r]     : w4[2 * r + 1];
      ull recv = __shfl_xor_sync(0xffffffffu, give, 2);
      w2[r] = add2(keep, recv);
    }
    ull keep = s2 ? w2[1] : w2[0];
    ull give = s2 ? w2[0] : w2[1];
    ull recv = __shfl_xor_sync(0xffffffffu, give, 4);
    ull tot = add2(keep, recv);

    float p = hsum2(tot) + xq_cur;
    h_old = 0.8f * h_old + 0.2f * fmaxf(p, 0.0f);
    shb[(rp ^ 1) * 576 + bf * 288 + (jf >> 5) * 36 + (jf & 31)] = h_old;
    xq_cur = xq_nxt;
    __syncthreads();
  }

  const float* hf0 = shb;
  const float* hf1 = shb + 288;
  float* out_actor  = out;
  float* out_critic = out + BB * AA;
  float* out_hx     = out + BB * AA + BB;

  if (tid < HH) {
    int pj = (tid >> 5) * 36 + (tid & 31);
    out_hx[b0g * HH + tid]       = hf0[pj];
    out_hx[(b0g + 1) * HH + tid] = hf1[pj];
  }

  const int wid = tid >> 5, lane = tid & 31;
  if (wid < AA) {
    float pa0 = 0.f, pa1 = 0.f;
    for (int jj = lane; jj < HH; jj += 32) {
      int pj = (jj >> 5) * 36 + (jj & 31);
      float wa = W_actor[wid * HH + jj];
      pa0 += wa * hf0[pj];
      pa1 += wa * hf1[pj];
    }
    #pragma unroll
    for (int off = 16; off; off >>= 1) {
      pa0 += __shfl_down_sync(0xffffffffu, pa0, off);
      pa1 += __shfl_down_sync(0xffffffffu, pa1, off);
    }
    if (lane == 0) {
      out_actor[b0g * AA + wid]       = pa0;
      out_actor[(b0g + 1) * AA + wid] = pa1;
    }
  }
  if (wid == 8) {
    float pc0 = 0.f, pc1 = 0.f;
    for (int jj = lane; jj < HH; jj += 32) {
      int pj = (jj >> 5) * 36 + (jj & 31);
      float wc = W_critic[jj];
      pc0 += wc * hf0[pj];
      pc1 += wc * hf1[pj];
    }
    #pragma unroll
    for (int off = 16; off; off >>= 1) {
      pc0 += __shfl_down_sync(0xffffffffu, pc0, off);
      pc1 += __shfl_down_sync(0xffffffffu, pc1, off);
    }
    if (lane == 0) {
      out_critic[b0g]     = pc0;
      out_critic[b0g + 1] = pc1;
    }
  }
}

// ---------------------------------------------------------------------------
extern "C" void kernel_launch(void* const* d_in, const int* in_sizes, int n_in,
                              void* d_out, int out_size) {
  const float* x        = (const float*)d_in[0];
  const float* hx       = (const float*)d_in[1];
  const float* W_ih     = (const float*)d_in[2];
  const float* W_hh     = (const float*)d_in[3];
  const float* W_actor  = (const float*)d_in[4];
  const float* W_critic = (const float*)d_in[5];
  float* out = (float*)d_out;

  const int smem1 = (2 * 128 * XSTR + 2 * 256 * XSTR) * 2;  // 208896 B
  const int smem2 = 98304 + 4608;

  cudaFuncSetAttribute(xproj_kernel,
                       cudaFuncAttributeMaxDynamicSharedMemorySize, smem1);
  cudaFuncSetAttribute(recurrence_kernel,
                       cudaFuncAttributeMaxDynamicSharedMemorySize, smem2);

  splitw_kernel<<<32, 512>>>(W_ih);
  xproj_kernel<<<(BB * TT) / 128, 512, smem1>>>(x);
  recurrence_kernel<<<BB / 2, 512, smem2>>>(hx, W_hh, W_actor, W_critic, out);
}